// round 17
// baseline (speedup 1.0000x reference)
#include <cuda_runtime.h>
#include <cuda_fp16.h>
#include <math.h>
#include <stdint.h>

#define D_     1024
#define H_     16
#define HD_    64
#define FF_    4096
#define B_     2
#define S_     2048
#define T_     (B_*S_)
#define EPS_   1e-5f

// ---------------- scratch (device globals; allocation-free) ----------------
__device__ __half g_h  [T_ * D_];
__device__ __half g_qkv[T_ * 3 * D_];
__device__ __half g_ctx[T_ * D_];
__device__ float  g_x1 [T_ * D_];
__device__ __half g_h2 [T_ * D_];
__device__ __half g_m  [T_ * FF_];
__device__ __half g_wqkv[3 * D_ * D_];
__device__ __half g_wo  [D_ * D_];
__device__ __half g_w1  [FF_ * D_];
__device__ __half g_w2  [D_ * FF_];

// ---------------- helpers ---------------------------------------------------
__device__ __forceinline__ uint32_t smem_u32(const void* p) {
    uint32_t a;
    asm("{ .reg .u64 t; cvta.to.shared.u64 t, %1; cvt.u32.u64 %0, t; }" : "=r"(a) : "l"(p));
    return a;
}
__device__ __forceinline__ float gelu_f(float x) {
    const float c = 0.7978845608028654f;
    float x3 = x * x * x;
    return 0.5f * x * (1.0f + tanhf(c * (x + 0.044715f * x3)));
}
__device__ __forceinline__ void cp16(uint32_t dst, const void* src) {
    asm volatile("cp.async.cg.shared.global [%0], [%1], 16;" :: "r"(dst), "l"(src) : "memory");
}
__device__ __forceinline__ void mma_f16(float& c0, float& c1, float& c2, float& c3,
                                        uint32_t a0, uint32_t a1, uint32_t a2, uint32_t a3,
                                        uint32_t b0, uint32_t b1) {
    asm volatile(
        "mma.sync.aligned.m16n8k16.row.col.f32.f16.f16.f32 "
        "{%0,%1,%2,%3}, {%4,%5,%6,%7}, {%8,%9}, {%0,%1,%2,%3};"
        : "+f"(c0), "+f"(c1), "+f"(c2), "+f"(c3)
        : "r"(a0), "r"(a1), "r"(a2), "r"(a3), "r"(b0), "r"(b1));
}
__device__ __forceinline__ float ex2f(float x) {
    float r;
    asm("ex2.approx.f32 %0, %1;" : "=f"(r) : "f"(x));
    return r;
}
__device__ __forceinline__ void ldsm_x4(uint32_t& r0, uint32_t& r1, uint32_t& r2, uint32_t& r3,
                                        uint32_t addr) {
    asm volatile("ldmatrix.sync.aligned.m8n8.x4.shared.b16 {%0,%1,%2,%3}, [%4];"
                 : "=r"(r0), "=r"(r1), "=r"(r2), "=r"(r3) : "r"(addr));
}
__device__ __forceinline__ void ldsm_x4_t(uint32_t& r0, uint32_t& r1, uint32_t& r2, uint32_t& r3,
                                          uint32_t addr) {
    asm volatile("ldmatrix.sync.aligned.m8n8.x4.trans.shared.b16 {%0,%1,%2,%3}, [%4];"
                 : "=r"(r0), "=r"(r1), "=r"(r2), "=r"(r3) : "r"(addr));
}

// ---------------- generic fp16 rounding (MLP-4 grid-stride) -----------------
__global__ __launch_bounds__(256) void round_w_kernel(const float* __restrict__ in,
                                                      __half* __restrict__ out, int n4) {
    const int stride = gridDim.x * 256;
    const int base = blockIdx.x * 256 + threadIdx.x;
    float4 v[4]; int idx[4]; bool ok[4];
    #pragma unroll
    for (int k = 0; k < 4; k++) {
        idx[k] = base + k * stride;
        ok[k] = idx[k] < n4;
        if (ok[k]) v[k] = ((const float4*)in)[idx[k]];
    }
    #pragma unroll
    for (int k = 0; k < 4; k++) {
        if (ok[k]) {
            __half2 h0 = __halves2half2(__float2half_rn(v[k].x), __float2half_rn(v[k].y));
            __half2 h1 = __halves2half2(__float2half_rn(v[k].z), __float2half_rn(v[k].w));
            ((__half2*)out)[2*idx[k]]   = h0;
            ((__half2*)out)[2*idx[k]+1] = h1;
        }
    }
}

// ---------------- LayerNorm (ddof=1, eps added to std), fp16 out -----------
__global__ __launch_bounds__(256) void ln_kernel(
    const float* __restrict__ x, const float* __restrict__ scale,
    const float* __restrict__ shift, __half* __restrict__ out)
{
    const int row = blockIdx.x;
    const int tid = threadIdx.x;
    const float4 v = ((const float4*)(x + (size_t)row * D_))[tid];

    float s  = v.x + v.y + v.z + v.w;
    float ss = v.x*v.x + v.y*v.y + v.z*v.z + v.w*v.w;
    #pragma unroll
    for (int o = 16; o > 0; o >>= 1) {
        s  += __shfl_xor_sync(0xffffffffu, s,  o);
        ss += __shfl_xor_sync(0xffffffffu, ss, o);
    }
    __shared__ float sm[8], sm2[8];
    const int w = tid >> 5, l = tid & 31;
    if (l == 0) { sm[w] = s; sm2[w] = ss; }
    __syncthreads();
    float ts = 0.f, tss = 0.f;
    #pragma unroll
    for (int i = 0; i < 8; i++) { ts += sm[i]; tss += sm2[i]; }

    const float mean = ts * (1.0f / D_);
    const float var  = (tss - (float)D_ * mean * mean) * (1.0f / (D_ - 1));
    const float inv  = 1.0f / (sqrtf(var) + EPS_);

    const float4 sc = ((const float4*)scale)[tid];
    const float4 sh = ((const float4*)shift)[tid];
    __half2 o0 = __halves2half2(__float2half_rn(sh.x + sc.x * (v.x - mean) * inv),
                                __float2half_rn(sh.y + sc.y * (v.y - mean) * inv));
    __half2 o1 = __halves2half2(__float2half_rn(sh.z + sc.z * (v.z - mean) * inv),
                                __float2half_rn(sh.w + sc.w * (v.w - mean) * inv));
    ((__half2*)(out + (size_t)row * D_))[2*tid]   = o0;
    ((__half2*)(out + (size_t)row * D_))[2*tid+1] = o1;
}

// ---------------- FP16 mma.sync NT GEMM: C[M,N] = A[M,K] . B[N,K]^T --------
#define BM 128
#define BN 256
#define BK 64
#define PADH 72
#define ASTRH (BM*PADH)
#define BSTRH (BN*PADH)
#define STAGEH (ASTRH + BSTRH)
#define NSTAGE 3
#define GEMM_SMEM (NSTAGE*STAGEH*2)
#define GTHREADS 256

__device__ __forceinline__ void stage_load(uint32_t smbase, int s,
                                           const __half* __restrict__ Ab,
                                           const __half* __restrict__ Bb,
                                           int K, int k0, int tid) {
    const uint32_t abase = smbase + (uint32_t)s * STAGEH * 2;
    const uint32_t bbase = abase + ASTRH * 2;
    #pragma unroll
    for (int i = 0; i < 4; i++) {
        int idx = i * GTHREADS + tid;
        int r = idx >> 3, g = idx & 7;
        cp16(abase + r * 144 + g * 16, Ab + (size_t)r * K + k0 + g * 8);
    }
    #pragma unroll
    for (int i = 0; i < 8; i++) {
        int idx = i * GTHREADS + tid;
        int r = idx >> 3, g = idx & 7;
        cp16(bbase + r * 144 + g * 16, Bb + (size_t)r * K + k0 + g * 8);
    }
}

template<bool BIAS, bool GELU_ACT, bool RES, bool OUTH>
__global__ __launch_bounds__(GTHREADS, 1) void gemm_mma(
    const __half* __restrict__ A, const __half* __restrict__ B,
    const float* __restrict__ bias, const float* __restrict__ res,
    void* __restrict__ Cv, int M, int N, int K)
{
    extern __shared__ __half smh[];
    const uint32_t smbase = smem_u32(smh);
    const int tid  = threadIdx.x;
    const int wid  = tid >> 5, lane = tid & 31;
    const int wm   = wid >> 2, wn = wid & 3;
    const int g    = lane >> 2, t = lane & 3;
    const int lane_lo = lane & 7, grp = lane >> 3;

    const __half* Ab = A + (size_t)blockIdx.y * BM * K;
    const __half* Bb = B + (size_t)blockIdx.x * BN * K;

    const uint32_t a_base = (uint32_t)(((wm * 64 + (grp & 1) * 8 + lane_lo) * PADH
                                        + (grp >> 1) * 8) * 2);
    const uint32_t b_base = (uint32_t)(((wn * 64 + (grp >> 1) * 8 + lane_lo) * PADH
                                        + (grp & 1) * 8) * 2) + ASTRH * 2;

    float acc[4][8][4];
    #pragma unroll
    for (int i = 0; i < 4; i++)
        #pragma unroll
        for (int j = 0; j < 8; j++)
            #pragma unroll
            for (int q = 0; q < 4; q++) acc[i][j][q] = 0.f;

    const int nch = K >> 6;

    stage_load(smbase, 0, Ab, Bb, K, 0, tid);
    asm volatile("cp.async.commit_group;" ::: "memory");
    stage_load(smbase, 1, Ab, Bb, K, BK, tid);
    asm volatile("cp.async.commit_group;" ::: "memory");

    for (int i = 0; i < nch; i++) {
        const int s = i % NSTAGE;
        if (i + 2 < nch) {
            asm volatile("cp.async.wait_group 1;" ::: "memory");
        } else {
            asm volatile("cp.async.wait_group 0;" ::: "memory");
        }
        __syncthreads();
        if (i + 2 < nch) {
            stage_load(smbase, (i + 2) % NSTAGE, Ab, Bb, K, (i + 2) * BK, tid);
            asm volatile("cp.async.commit_group;" ::: "memory");
        }

        const uint32_t stg = smbase + (uint32_t)s * STAGEH * 2;
        const uint32_t abase = stg + a_base;
        const uint32_t bbase = stg + b_base;

        #pragma unroll
        for (int ks = 0; ks < 4; ks++) {
            const uint32_t koff = (uint32_t)(ks * 16 * 2);
            uint32_t af[4][4], bf[8][2];
            #pragma unroll
            for (int mt = 0; mt < 4; mt++)
                ldsm_x4(af[mt][0], af[mt][1], af[mt][2], af[mt][3],
                        abase + (uint32_t)(mt * 16 * PADH * 2) + koff);
            #pragma unroll
            for (int np = 0; np < 4; np++)
                ldsm_x4(bf[2*np][0], bf[2*np][1], bf[2*np+1][0], bf[2*np+1][1],
                        bbase + (uint32_t)(np * 16 * PADH * 2) + koff);
            #pragma unroll
            for (int mt = 0; mt < 4; mt++)
                #pragma unroll
                for (int nt = 0; nt < 8; nt++)
                    mma_f16(acc[mt][nt][0], acc[mt][nt][1], acc[mt][nt][2], acc[mt][nt][3],
                            af[mt][0], af[mt][1], af[mt][2], af[mt][3],
                            bf[nt][0], bf[nt][1]);
        }
    }

    #pragma unroll
    for (int mt = 0; mt < 4; mt++) {
        const int r0 = blockIdx.y * BM + wm * 64 + mt * 16 + g;
        #pragma unroll
        for (int nt = 0; nt < 8; nt++) {
            const int c0 = blockIdx.x * BN + wn * 64 + nt * 8 + 2 * t;
            float b0 = 0.f, b1 = 0.f;
            if (BIAS) { b0 = bias[c0]; b1 = bias[c0 + 1]; }
            float v00 = acc[mt][nt][0] + b0, v01 = acc[mt][nt][1] + b1;
            float v10 = acc[mt][nt][2] + b0, v11 = acc[mt][nt][3] + b1;
            if (GELU_ACT) { v00 = gelu_f(v00); v01 = gelu_f(v01);
                            v10 = gelu_f(v10); v11 = gelu_f(v11); }
            if (RES) {
                const float2 r0v = *(const float2*)(res + (size_t)r0 * N + c0);
                const float2 r1v = *(const float2*)(res + (size_t)(r0 + 8) * N + c0);
                v00 += r0v.x; v01 += r0v.y; v10 += r1v.x; v11 += r1v.y;
            }
            if (OUTH) {
                __half* C = (__half*)Cv;
                *(__half2*)(C + (size_t)r0 * N + c0) =
                    __halves2half2(__float2half_rn(v00), __float2half_rn(v01));
                *(__half2*)(C + (size_t)(r0 + 8) * N + c0) =
                    __halves2half2(__float2half_rn(v10), __float2half_rn(v11));
            } else {
                float* C = (float*)Cv;
                *(float2*)(C + (size_t)r0 * N + c0)       = make_float2(v00, v01);
                *(float2*)(C + (size_t)(r0 + 8) * N + c0) = make_float2(v10, v11);
            }
        }
    }
}

// ---------------- FP16 tensor-core causal flash attention (HD=64) ----------
#define AQT 128
#define AKT 64
#define KPADH 72
#define VPADH 72
#define PPADH 72
#define L2OFF 11.541560327111708f
#define ONESH2 0x3C003C00u
#define ATTN_SMEM ((2*AKT*KPADH + 2*AKT*VPADH + AQT*PPADH) * 2)

__global__ __launch_bounds__(256, 2) void attn_tc(
    const __half* __restrict__ qkv, __half* __restrict__ ctx)
{
    extern __shared__ __half smh_a[];
    __half* kb[2]; __half* vb[2];
    kb[0] = smh_a;
    kb[1] = kb[0] + AKT * KPADH;
    vb[0] = kb[1] + AKT * KPADH;
    vb[1] = vb[0] + AKT * VPADH;
    __half* ps = vb[1] + AKT * VPADH;

    const int qt  = (int)gridDim.x - 1 - (int)blockIdx.x;
    const int bh  = blockIdx.y;
    const int b   = bh >> 4;
    const int h   = bh & 15;
    const int tid = threadIdx.x;
    const int w   = tid >> 5, lane = tid & 31;
    const int g   = lane >> 2, t = lane & 3;
    const int mrow = w * 16;
    const int bS  = b * S_;
    const int tok0 = bS + qt * AQT;

    const __half2 qsc = __half2half2(__float2half(0.18033688011112042f));
    for (int i = tid; i < AQT * 8; i += 256) {
        const int r = i >> 3, c = i & 7;
        uint4 v = *(const uint4*)(qkv + (size_t)(tok0 + r) * (3 * D_) + h * HD_ + c * 8);
        __half2* pv = (__half2*)&v;
        pv[0] = __hmul2(pv[0], qsc); pv[1] = __hmul2(pv[1], qsc);
        pv[2] = __hmul2(pv[2], qsc); pv[3] = __hmul2(pv[3], qsc);
        *(uint4*)(ps + r * PPADH + c * 8) = v;
    }
    __syncthreads();
    uint32_t qf[4][4];
    #pragma unroll
    for (int kc = 0; kc < 4; kc++) {
        const int k0 = kc * 16;
        qf[kc][0] = *(const uint32_t*)(ps + (mrow + g)     * PPADH + k0 + 2 * t);
        qf[kc][1] = *(const uint32_t*)(ps + (mrow + g + 8) * PPADH + k0 + 2 * t);
        qf[kc][2] = *(const uint32_t*)(ps + (mrow + g)     * PPADH + k0 + 2 * t + 8);
        qf[kc][3] = *(const uint32_t*)(ps + (mrow + g + 8) * PPADH + k0 + 2 * t + 8);
    }

    float o[8][4];
    #pragma unroll
    for (int nt = 0; nt < 8; nt++)
        #pragma unroll
        for (int q = 0; q < 4; q++) o[nt][q] = 0.f;
    float lacc[4] = {0.f, 0.f, 0.f, 0.f};

    const int ntiles = 2 * qt + 2;
    const int qrow0 = qt * AQT + mrow + g;
    const int qrow1 = qrow0 + 8;
    const int qrow_hi = qt * AQT + mrow + 15;

    const int lane_lo = lane & 7, grp = lane >> 3;
    const uint32_t kfragoff = (uint32_t)((((grp >> 1) * 8 + lane_lo) * KPADH + (grp & 1) * 8) * 2);
    const uint32_t vfragoff = (uint32_t)((((grp & 1) * 8 + lane_lo) * VPADH + (grp >> 1) * 8) * 2);

    {
        const uint32_t ka = smem_u32(kb[0]), va = smem_u32(vb[0]);
        #pragma unroll
        for (int i = 0; i < 2; i++) {
            const int idx = i * 256 + tid;
            const int r = idx >> 3, c = idx & 7;
            const size_t base = (size_t)(bS + r) * (3 * D_) + h * HD_ + c * 8;
            cp16(ka + r * (KPADH * 2) + c * 16, qkv + base + D_);
            cp16(va + r * (VPADH * 2) + c * 16, qkv + base + 2 * D_);
        }
        asm volatile("cp.async.commit_group;" ::: "memory");
    }

    for (int j = 0; j < ntiles; j++) {
        __syncthreads();
        if (j + 1 < ntiles) {
            const int nb = (j + 1) & 1;
            const uint32_t ka = smem_u32(kb[nb]), va = smem_u32(vb[nb]);
            #pragma unroll
            for (int i = 0; i < 2; i++) {
                const int idx = i * 256 + tid;
                const int r = idx >> 3, c = idx & 7;
                const size_t base = (size_t)(bS + (j + 1) * AKT + r) * (3 * D_) + h * HD_ + c * 8;
                cp16(ka + r * (KPADH * 2) + c * 16, qkv + base + D_);
                cp16(va + r * (VPADH * 2) + c * 16, qkv + base + 2 * D_);
            }
            asm volatile("cp.async.commit_group;" ::: "memory");
            asm volatile("cp.async.wait_group 1;" ::: "memory");
        } else {
            asm volatile("cp.async.wait_group 0;" ::: "memory");
        }
        __syncthreads();

        const int k0abs = j * AKT;
        if (k0abs > qrow_hi) continue;   // warp-uniform: tile fully masked

        const uint32_t kbase = smem_u32(kb[j & 1]) + kfragoff;
        const uint32_t vbase = smem_u32(vb[j & 1]) + vfragoff;

        float sa[8][4];
        #pragma unroll
        for (int nt = 0; nt < 8; nt++)
            #pragma unroll
            for (int q = 0; q < 4; q++) sa[nt][q] = -1e30f;   // masked default

        #pragma unroll
        for (int np = 0; np < 4; np++) {
            if (k0abs + np * 16 <= qrow_hi) {                 // warp-uniform
                float s0[4] = {0.f,0.f,0.f,0.f}, s1[4] = {0.f,0.f,0.f,0.f};
                #pragma unroll
                for (int kc = 0; kc < 4; kc++) {
                    uint32_t r0, r1, r2, r3;
                    ldsm_x4(r0, r1, r2, r3,
                            kbase + (uint32_t)((np * 16 * KPADH + kc * 16) * 2));
                    mma_f16(s0[0], s0[1], s0[2], s0[3],
                            qf[kc][0], qf[kc][1], qf[kc][2], qf[kc][3], r0, r1);
                    mma_f16(s1[0], s1[1], s1[2], s1[3],
                            qf[kc][0], qf[kc][1], qf[kc][2], qf[kc][3], r2, r3);
                }
                #pragma unroll
                for (int q = 0; q < 4; q++) { sa[2*np][q] = s0[q]; sa[2*np+1][q] = s1[q]; }
            }
        }

        if (j >= 2 * qt) {
            #pragma unroll
            for (int nt = 0; nt < 8; nt++) {
                const int col = k0abs + nt * 8 + 2 * t;
                if (col     > qrow0) sa[nt][0] = -1e30f;
                if (col + 1 > qrow0) sa[nt][1] = -1e30f;
                if (col     > qrow1) sa[nt][2] = -1e30f;
                if (col + 1 > qrow1) sa[nt][3] = -1e30f;
            }
        }

        #pragma unroll
        for (int kc = 0; kc < 4; kc++) {
            if (k0abs + kc * 16 > qrow_hi) continue;          // warp-uniform
            const float e00 = ex2f(sa[2*kc][0]   - L2OFF);
            const float e01 = ex2f(sa[2*kc][1]   - L2OFF);
            const float e02 = ex2f(sa[2*kc][2]   - L2OFF);
            const float e03 = ex2f(sa[2*kc][3]   - L2OFF);
            const float e10 = ex2f(sa[2*kc+1][0] - L2OFF);
            const float e11 = ex2f(sa[2*kc+1][1] - L2OFF);
            const float e12 = ex2f(sa[2*kc+1][2] - L2OFF);
            const float e13 = ex2f(sa[2*kc+1][3] - L2OFF);
            __half2 ha0 = __halves2half2(__float2half_rn(e00), __float2half_rn(e01));
            __half2 ha1 = __halves2half2(__float2half_rn(e02), __float2half_rn(e03));
            __half2 ha2 = __halves2half2(__float2half_rn(e10), __float2half_rn(e11));
            __half2 ha3 = __halves2half2(__float2half_rn(e12), __float2half_rn(e13));
            const uint32_t a0 = *(uint32_t*)&ha0;
            const uint32_t a1 = *(uint32_t*)&ha1;
            const uint32_t a2 = *(uint32_t*)&ha2;
            const uint32_t a3 = *(uint32_t*)&ha3;
            mma_f16(lacc[0], lacc[1], lacc[2], lacc[3], a0, a1, a2, a3, ONESH2, ONESH2);
            #pragma unroll
            for (int np = 0; np < 4; np++) {
                uint32_t r0, r1, r2, r3;
                ldsm_x4_t(r0, r1, r2, r3,
                          vbase + (uint32_t)((kc * 16 * VPADH + np * 16) * 2));
                mma_f16(o[2*np][0], o[2*np][1], o[2*np][2], o[2*np][3],
                        a0, a1, a2, a3, r0, r1);
                mma_f16(o[2*np+1][0], o[2*np+1][1], o[2*np+1][2], o[2*np+1][3],
                        a0, a1, a2, a3, r2, r3);
            }
        }
    }

    const float il0 = 1.0f / lacc[0], il1 = 1.0f / lacc[2];
    const int row0 = tok0 + mrow + g;
    #pragma unroll
    for (int nt = 0; nt < 8; nt++) {
        const int col = h * HD_ + nt * 8 + 2 * t;
        *(__half2*)(ctx + (size_t)row0 * D_ + col) =
            __halves2half2(__float2half_rn(o[nt][0] * il0), __float2half_rn(o[nt][1] * il0));
        *(__half2*)(ctx + (size_t)(row0 + 8) * D_ + col) =
            __halves2half2(__float2half_rn(o[nt][2] * il1), __float2half_rn(o[nt][3] * il1));
    }
}

// ---------------- launch ---------------------------------------------------
extern "C" void kernel_launch(void* const* d_in, const int* in_sizes, int n_in,
                              void* d_out, int out_size)
{
    const float* x      = (const float*)d_in[0];
    const float* scale1 = (const float*)d_in[1];
    const float* shift1 = (const float*)d_in[2];
    const float* Wqkv   = (const float*)d_in[3];
    const float* Wo_w   = (const float*)d_in[4];
    const float* Wo_b   = (const float*)d_in[5];
    const float* scale2 = (const float*)d_in[6];
    const float* shift2 = (const float*)d_in[7];
    const float* W1     = (const float*)d_in[8];
    const float* b1     = (const float*)d_in[9];
    const float* W2     = (const float*)d_in[10];
    const float* b2     = (const float*)d_in[11];
    float* out = (float*)d_out;

    __half *h, *qkv, *ctx, *h2, *mbuf, *wqkv, *wo, *w1, *w2;
    float *x1;
    cudaGetSymbolAddress((void**)&h,    g_h);
    cudaGetSymbolAddress((void**)&qkv,  g_qkv);
    cudaGetSymbolAddress((void**)&ctx,  g_ctx);
    cudaGetSymbolAddress((void**)&x1,   g_x1);
    cudaGetSymbolAddress((void**)&h2,   g_h2);
    cudaGetSymbolAddress((void**)&mbuf, g_m);
    cudaGetSymbolAddress((void**)&wqkv, g_wqkv);
    cudaGetSymbolAddress((void**)&wo,   g_wo);
    cudaGetSymbolAddress((void**)&w1,   g_w1);
    cudaGetSymbolAddress((void**)&w2,   g_w2);

    cudaFuncSetAttribute(attn_tc, cudaFuncAttributeMaxDynamicSharedMemorySize, ATTN_SMEM);
    cudaFuncSetAttribute(gemm_mma<false,false,false,true>, cudaFuncAttributeMaxDynamicSharedMemorySize, GEMM_SMEM);
    cudaFuncSetAttribute(gemm_mma<true,false,true,false>,  cudaFuncAttributeMaxDynamicSharedMemorySize, GEMM_SMEM);
    cudaFuncSetAttribute(gemm_mma<true,true,false,true>,   cudaFuncAttributeMaxDynamicSharedMemorySize, GEMM_SMEM);

    static cudaStream_t s2 = nullptr;
    static cudaEvent_t ev_fork = nullptr, ev_qkvw = nullptr, ev_join = nullptr;
    if (!s2) {
        cudaStreamCreateWithFlags(&s2, cudaStreamNonBlocking);
        cudaEventCreateWithFlags(&ev_fork, cudaEventDisableTiming);
        cudaEventCreateWithFlags(&ev_qkvw, cudaEventDisableTiming);
        cudaEventCreateWithFlags(&ev_join, cudaEventDisableTiming);
    }

    // fork: weight rounding on side stream, LN1 on main stream (independent)
    cudaEventRecord(ev_fork, 0);
    cudaStreamWaitEvent(s2, ev_fork, 0);
    round_w_kernel<<<(3*D_*D_/4 + 1023)/1024, 256, 0, s2>>>(Wqkv, wqkv, 3*D_*D_/4);
    cudaEventRecord(ev_qkvw, s2);
    round_w_kernel<<<(D_*D_/4  + 1023)/1024, 256, 0, s2>>>(Wo_w, wo, D_*D_/4);
    round_w_kernel<<<(FF_*D_/4 + 1023)/1024, 256, 0, s2>>>(W1,   w1, FF_*D_/4);
    round_w_kernel<<<(D_*FF_/4 + 1023)/1024, 256, 0, s2>>>(W2,   w2, D_*FF_/4);
    cudaEventRecord(ev_join, s2);

    // 1. LN1 -> fp16 (overlapped with wqkv rounding)
    ln_kernel<<<T_, 256>>>(x, scale1, shift1, h);

    // join wqkv before QKV GEMM
    cudaStreamWaitEvent(0, ev_qkvw, 0);
    // 2. QKV = h @ Wqkv^T -> fp16
    gemm_mma<false,false,false,true><<<dim3(3*D_/BN, T_/BM), GTHREADS, GEMM_SMEM>>>(
        h, wqkv, nullptr, nullptr, qkv, T_, 3*D_, D_);
    // 3. fp16 tensor-core causal attention -> ctx fp16
    attn_tc<<<dim3(S_/AQT, B_*H_), 256, ATTN_SMEM>>>(qkv, ctx);

    // join remaining weights before Wo
    cudaStreamWaitEvent(0, ev_join, 0);

    // 4. x1 = x + ctx @ Wo^T + Wo_b -> fp32
    gemm_mma<true,false,true,false><<<dim3(D_/BN, T_/BM), GTHREADS, GEMM_SMEM>>>(
        ctx, wo, Wo_b, x, x1, T_, D_, D_);
    // 5. LN2 -> fp16
    ln_kernel<<<T_, 256>>>(x1, scale2, shift2, h2);
    // 6. m = gelu(h2 @ W1^T + b1) -> fp16
    gemm_mma<true,true,false,true><<<dim3(FF_/BN, T_/BM), GTHREADS, GEMM_SMEM>>>(
        h2, w1, b1, nullptr, mbuf, T_, FF_, D_);
    // 7. out = x1 + m @ W2^T + b2 -> fp32
    gemm_mma<true,false,true,false><<<dim3(D_/BN, T_/BM), GTHREADS, GEMM_SMEM>>>(
        mbuf, w2, b2, x1, out, T_, D_, FF_);
}